// round 8
// baseline (speedup 1.0000x reference)
#include <cuda_runtime.h>

// VectorQuantizer: N=262144 points (D=64), K=1024 codes.
// out = [ z_q (N*64 floats) | encoding_inds as float (N) ]
//
// Round 7: R4's 8x8 fma2 register tile + conflict-free z (ROWF=66), plus:
//  - codebook tiles double-buffered via cp.async (16B, XOR-swizzled chunks:
//    phys q^(kc&7) on natural 256B rows -> aligned stores AND conflict-free
//    broadcast LDS.128 reads), staging overlapped with compute
//  - one __syncthreads per tile
//  - inner loop per 16B chunk (2 dim-pairs): 16 LDS.64 (z) + 8 LDS.128 (cb)
//    -> 128 fma2
// Score keeps reference rounding exactly:
//   dist2 = fl( fl(zsq - 2*dot) + cb_sq ), argmin first-index tie-break.

#define DIMS    64
#define KCODES  1024
#define TPB     256
#define PTB     128               // points per block
#define TILE_C  128               // codes per smem tile
#define NTILES  (KCODES / TILE_C) // 8
#define ROWF    66                // z row stride (floats), 66%32=2

// SMEM float offsets
#define OFF_Z    0                          // PTB*ROWF = 8448
#define OFF_CSQ  (PTB * ROWF)               // 1024
#define OFF_ZSQ  (OFF_CSQ + KCODES)         // 128
#define OFF_CB   ((OFF_ZSQ + PTB + 3) & ~3) // 2 * TILE_C*DIMS = 16384 (16B aligned)
#define SMEM_FLOATS (OFF_CB + 2 * TILE_C * DIMS)
#define SMEM_BYTES  (SMEM_FLOATS * 4)       // ~104 KB

typedef unsigned long long u64;
typedef unsigned int u32;

__device__ float g_cbsq[KCODES];

static __device__ __forceinline__ void unpack2(u64 v, float& lo, float& hi) {
    u32 a, b;
    asm("mov.b64 {%0, %1}, %2;" : "=r"(a), "=r"(b) : "l"(v));
    lo = __uint_as_float(a);
    hi = __uint_as_float(b);
}
static __device__ __forceinline__ u64 fma2(u64 a, u64 b, u64 c) {
    u64 d;
    asm("fma.rn.f32x2 %0, %1, %2, %3;" : "=l"(d) : "l"(a), "l"(b), "l"(c));
    return d;
}
static __device__ __forceinline__ void cp_async16(u32 saddr, const void* gaddr) {
    asm volatile("cp.async.cg.shared.global [%0], [%1], 16;"
                 :: "r"(saddr), "l"(gaddr));
}
static __device__ __forceinline__ void cp_commit() {
    asm volatile("cp.async.commit_group;");
}
static __device__ __forceinline__ void cp_wait0() {
    asm volatile("cp.async.wait_group 0;" ::: "memory");
}

// ---------------------------------------------------------------------------
// cb_sq[k] = sequential fp32 sum of squares of codebook row k (matches ref).
__global__ void cbsq_kernel(const float* __restrict__ cb) {
    int k = blockIdx.x * blockDim.x + threadIdx.x;
    if (k < KCODES) {
        const float* r = cb + (size_t)k * DIMS;
        float s = 0.f;
#pragma unroll
        for (int i = 0; i < DIMS; i++)
            s = __fadd_rn(s, __fmul_rn(r[i], r[i]));
        g_cbsq[k] = s;
    }
}

// ---------------------------------------------------------------------------
__global__ __launch_bounds__(TPB, 1)
void vq_kernel(const float* __restrict__ z_e,
               const float* __restrict__ cb,
               float* __restrict__ out,
               int N) {
    extern __shared__ float smem[];
    float* s_z   = smem + OFF_Z;    // [PTB][ROWF]
    float* s_csq = smem + OFF_CSQ;  // [KCODES]
    float* s_zsq = smem + OFF_ZSQ;  // [PTB]
    float* s_cb  = smem + OFF_CB;   // 2 x [TILE_C][64], 16B-chunk swizzled

    const int tid = threadIdx.x;
    const int tx  = tid & 15;   // point lane: pts tx + p*16
    const int ty  = tid >> 4;   // code lane:  codes ty + c*16 (per tile)
    const int base = blockIdx.x * PTB;

    const u32 s_cb_u = (u32)__cvta_generic_to_shared(s_cb);
    const int kc_pf = tid >> 4;        // code row this thread prefetches
    const int q_pf  = tid & 15;        // 16B chunk index
    const u32 pf_dst_off = (u32)(kc_pf * 256 + ((q_pf ^ (kc_pf & 7)) << 4));
    const size_t pf_src_off = (size_t)kc_pf * DIMS + q_pf * 4;

    // --- prefetch codebook tile 0 into buffer 0 ---
#pragma unroll
    for (int i = 0; i < 8; i++) {
        // e = tid + i*256 -> kc = kc_pf + i*16, q = q_pf
        int kc = kc_pf + i * 16;
        u32 dst = s_cb_u + (u32)(kc * 256 + ((q_pf ^ (kc & 7)) << 4));
        cp_async16(dst, cb + (size_t)kc * DIMS + q_pf * 4);
    }
    cp_commit();

    // --- stage z tile [PTB x DIMS] into padded rows; also csq ---
    {
        const float4* z4 = (const float4*)z_e;
        const int lim4 = (N * DIMS) / 4;
#pragma unroll
        for (int i = 0; i < 8; i++) {
            int e  = tid + i * TPB;      // 0..2047
            int pt = e >> 4;
            int q  = e & 15;
            float4 v;
            int g = (base + pt) * 16 + q;
            if (g < lim4) v = z4[g];
            else { v.x = v.y = v.z = v.w = 0.f; }
            float* dst = s_z + pt * ROWF + q * 4;
            *(float2*)(dst)     = make_float2(v.x, v.y);
            *(float2*)(dst + 2) = make_float2(v.z, v.w);
        }
#pragma unroll
        for (int i = 0; i < 4; i++)
            s_csq[tid + i * TPB] = g_cbsq[tid + i * TPB];
    }
    __syncthreads();

    // zsq per point (sequential fp32, matches reference path)
    if (tid < PTB) {
        const float* zr = s_z + tid * ROWF;
        float s = 0.f;
#pragma unroll
        for (int i = 0; i < DIMS; i++)
            s = __fadd_rn(s, __fmul_rn(zr[i], zr[i]));
        s_zsq[tid] = s;
    }
    __syncthreads();

    float zsqr[8];
#pragma unroll
    for (int p = 0; p < 8; p++) zsqr[p] = s_zsq[tx + p * 16];

    float best[8];
    int   bidx[8];
#pragma unroll
    for (int p = 0; p < 8; p++) { best[p] = 3.4e38f; bidx[p] = 0; }

    const float* zbase = s_z + tx * ROWF;
    const int xsw = ty & 7;   // swizzle xor, warp-uniform per ty

    for (int t = 0; t < NTILES; ++t) {
        cp_wait0();
        __syncthreads();   // tile t resident; prior buffer reads all done

        // prefetch tile t+1 into the other buffer (overlaps compute below)
        if (t + 1 < NTILES) {
            u32 bufo = (u32)(((t + 1) & 1) * (TILE_C * DIMS * 4));
            const float* g = cb + (size_t)(t + 1) * TILE_C * DIMS;
#pragma unroll
            for (int i = 0; i < 8; i++) {
                int kc = kc_pf + i * 16;
                u32 dst = s_cb_u + bufo + (u32)(kc * 256 + ((q_pf ^ (kc & 7)) << 4));
                cp_async16(dst, g + (size_t)kc * DIMS + q_pf * 4);
            }
            cp_commit();
        }

        const float* cbuf = s_cb + (t & 1) * (TILE_C * DIMS) + ty * DIMS;

        u64 acc[8][8];
#pragma unroll
        for (int p = 0; p < 8; p++)
#pragma unroll
            for (int c = 0; c < 8; c++) acc[p][c] = 0ull;

#pragma unroll 4
        for (int dpc = 0; dpc < 16; ++dpc) {     // 16B chunk = dims 4dpc..4dpc+3
            u64 zv0[8], zv1[8];
#pragma unroll
            for (int p = 0; p < 8; p++) {
                const float* zp = zbase + p * (16 * ROWF) + dpc * 4;
                zv0[p] = *(const u64*)(zp);
                zv1[p] = *(const u64*)(zp + 2);
            }
            ulonglong2 cv[8];
            const int sq = (dpc ^ xsw) << 2;     // float offset in 64-float row
#pragma unroll
            for (int c = 0; c < 8; c++)
                cv[c] = *(const ulonglong2*)(cbuf + c * (16 * DIMS) + sq);
#pragma unroll
            for (int p = 0; p < 8; p++)
#pragma unroll
                for (int c = 0; c < 8; c++) {
                    acc[p][c] = fma2(zv0[p], cv[c].x, acc[p][c]);
                    acc[p][c] = fma2(zv1[p], cv[c].y, acc[p][c]);
                }
        }

        // epilogue: 64 dists, exact reference rounding
#pragma unroll
        for (int c = 0; c < 8; c++) {
            const int code = t * TILE_C + c * 16 + ty;
            const float csq = s_csq[code];
#pragma unroll
            for (int p = 0; p < 8; p++) {
                float lo, hi;
                unpack2(acc[p][c], lo, hi);
                float dot = __fadd_rn(lo, hi);
                float d = __fadd_rn(__fmaf_rn(-2.f, dot, zsqr[p]), csq);
                if (d < best[p]) { best[p] = d; bidx[p] = code; }
            }
        }
    }

    // --- cross-ty argmin: packed (dist_bits<<32)|idx u64 min (dist2 > 0) ---
    __syncthreads();
    u64* s_red = (u64*)s_cb;   // reuse cb buffers (needs 128*17*8 = 17408 B)
#pragma unroll
    for (int p = 0; p < 8; p++)
        s_red[(tx + p * 16) * 17 + ty] =
            (((u64)__float_as_uint(best[p])) << 32) | (u32)bidx[p];
    __syncthreads();

    int* s_idx = (int*)s_zsq;  // reuse zsq region (128 ints)
    if (tid < PTB) {
        u64 m = s_red[tid * 17];
#pragma unroll
        for (int j = 1; j < 16; j++) {
            u64 v = s_red[tid * 17 + j];
            if (v < m) m = v;
        }
        int idx = (int)(m & 0xffffffffu);
        s_idx[tid] = idx;
        if (base + tid < N)
            out[(size_t)N * DIMS + base + tid] = (float)idx;
    }
    __syncthreads();

    // --- gather z_q = codebook[idx] (bitwise exact) ---
    {
        const float4* cb4 = (const float4*)cb;
        float4* o4 = (float4*)out;
#pragma unroll
        for (int i = 0; i < 8; i++) {
            int e  = tid + i * TPB;
            int pt = e >> 4;
            int q  = e & 15;
            if (base + pt < N)
                o4[(size_t)(base + pt) * 16 + q] = cb4[(size_t)s_idx[pt] * 16 + q];
        }
    }
}

// ---------------------------------------------------------------------------
extern "C" void kernel_launch(void* const* d_in, const int* in_sizes, int n_in,
                              void* d_out, int out_size) {
    const float* z_e = (const float*)d_in[0];
    const float* cb  = (const float*)d_in[1];
    float* out = (float*)d_out;
    const int N = in_sizes[0] / DIMS;

    cbsq_kernel<<<(KCODES + 255) / 256, 256>>>(cb);

    cudaFuncSetAttribute(vq_kernel, cudaFuncAttributeMaxDynamicSharedMemorySize,
                         SMEM_BYTES);
    const int grid = (N + PTB - 1) / PTB;
    vq_kernel<<<grid, TPB, SMEM_BYTES>>>(z_e, cb, out, N);
}

// round 9
// speedup vs baseline: 1.0557x; 1.0557x over previous
#include <cuda_runtime.h>

// VectorQuantizer: N=262144 points (D=64), K=1024 codes.
// out = [ z_q (N*64 floats) | encoding_inds as float (N) ]
//
// Round 7: R4's 8x8 fma2 register tile + conflict-free z (ROWF=66), plus:
//  - codebook tiles double-buffered via cp.async (16B, XOR-swizzled chunks:
//    phys q^(kc&7) on natural 256B rows -> aligned stores AND conflict-free
//    broadcast LDS.128 reads), staging overlapped with compute
//  - one __syncthreads per tile
//  - inner loop per 16B chunk (2 dim-pairs): 16 LDS.64 (z) + 8 LDS.128 (cb)
//    -> 128 fma2
// Score keeps reference rounding exactly:
//   dist2 = fl( fl(zsq - 2*dot) + cb_sq ), argmin first-index tie-break.

#define DIMS    64
#define KCODES  1024
#define TPB     256
#define PTB     128               // points per block
#define TILE_C  128               // codes per smem tile
#define NTILES  (KCODES / TILE_C) // 8
#define ROWF    66                // z row stride (floats), 66%32=2

// SMEM float offsets
#define OFF_Z    0                          // PTB*ROWF = 8448
#define OFF_CSQ  (PTB * ROWF)               // 1024
#define OFF_ZSQ  (OFF_CSQ + KCODES)         // 128
#define OFF_CB   ((OFF_ZSQ + PTB + 3) & ~3) // 2 * TILE_C*DIMS = 16384 (16B aligned)
#define SMEM_FLOATS (OFF_CB + 2 * TILE_C * DIMS)
#define SMEM_BYTES  (SMEM_FLOATS * 4)       // ~104 KB

typedef unsigned long long u64;
typedef unsigned int u32;

__device__ float g_cbsq[KCODES];

static __device__ __forceinline__ void unpack2(u64 v, float& lo, float& hi) {
    u32 a, b;
    asm("mov.b64 {%0, %1}, %2;" : "=r"(a), "=r"(b) : "l"(v));
    lo = __uint_as_float(a);
    hi = __uint_as_float(b);
}
static __device__ __forceinline__ u64 fma2(u64 a, u64 b, u64 c) {
    u64 d;
    asm("fma.rn.f32x2 %0, %1, %2, %3;" : "=l"(d) : "l"(a), "l"(b), "l"(c));
    return d;
}
static __device__ __forceinline__ void cp_async16(u32 saddr, const void* gaddr) {
    asm volatile("cp.async.cg.shared.global [%0], [%1], 16;"
                 :: "r"(saddr), "l"(gaddr));
}
static __device__ __forceinline__ void cp_commit() {
    asm volatile("cp.async.commit_group;");
}
static __device__ __forceinline__ void cp_wait0() {
    asm volatile("cp.async.wait_group 0;" ::: "memory");
}

// ---------------------------------------------------------------------------
// cb_sq[k] = sequential fp32 sum of squares of codebook row k (matches ref).
__global__ void cbsq_kernel(const float* __restrict__ cb) {
    int k = blockIdx.x * blockDim.x + threadIdx.x;
    if (k < KCODES) {
        const float* r = cb + (size_t)k * DIMS;
        float s = 0.f;
#pragma unroll
        for (int i = 0; i < DIMS; i++)
            s = __fadd_rn(s, __fmul_rn(r[i], r[i]));
        g_cbsq[k] = s;
    }
}

// ---------------------------------------------------------------------------
__global__ __launch_bounds__(TPB, 1)
void vq_kernel(const float* __restrict__ z_e,
               const float* __restrict__ cb,
               float* __restrict__ out,
               int N) {
    extern __shared__ float smem[];
    float* s_z   = smem + OFF_Z;    // [PTB][ROWF]
    float* s_csq = smem + OFF_CSQ;  // [KCODES]
    float* s_zsq = smem + OFF_ZSQ;  // [PTB]
    float* s_cb  = smem + OFF_CB;   // 2 x [TILE_C][64], 16B-chunk swizzled

    const int tid = threadIdx.x;
    const int tx  = tid & 15;   // point lane: pts tx + p*16
    const int ty  = tid >> 4;   // code lane:  codes ty + c*16 (per tile)
    const int base = blockIdx.x * PTB;

    const u32 s_cb_u = (u32)__cvta_generic_to_shared(s_cb);
    const int kc_pf = tid >> 4;        // code row this thread prefetches
    const int q_pf  = tid & 15;        // 16B chunk index
    const u32 pf_dst_off = (u32)(kc_pf * 256 + ((q_pf ^ (kc_pf & 7)) << 4));
    const size_t pf_src_off = (size_t)kc_pf * DIMS + q_pf * 4;

    // --- prefetch codebook tile 0 into buffer 0 ---
#pragma unroll
    for (int i = 0; i < 8; i++) {
        // e = tid + i*256 -> kc = kc_pf + i*16, q = q_pf
        int kc = kc_pf + i * 16;
        u32 dst = s_cb_u + (u32)(kc * 256 + ((q_pf ^ (kc & 7)) << 4));
        cp_async16(dst, cb + (size_t)kc * DIMS + q_pf * 4);
    }
    cp_commit();

    // --- stage z tile [PTB x DIMS] into padded rows; also csq ---
    {
        const float4* z4 = (const float4*)z_e;
        const int lim4 = (N * DIMS) / 4;
#pragma unroll
        for (int i = 0; i < 8; i++) {
            int e  = tid + i * TPB;      // 0..2047
            int pt = e >> 4;
            int q  = e & 15;
            float4 v;
            int g = (base + pt) * 16 + q;
            if (g < lim4) v = z4[g];
            else { v.x = v.y = v.z = v.w = 0.f; }
            float* dst = s_z + pt * ROWF + q * 4;
            *(float2*)(dst)     = make_float2(v.x, v.y);
            *(float2*)(dst + 2) = make_float2(v.z, v.w);
        }
#pragma unroll
        for (int i = 0; i < 4; i++)
            s_csq[tid + i * TPB] = g_cbsq[tid + i * TPB];
    }
    __syncthreads();

    // zsq per point (sequential fp32, matches reference path)
    if (tid < PTB) {
        const float* zr = s_z + tid * ROWF;
        float s = 0.f;
#pragma unroll
        for (int i = 0; i < DIMS; i++)
            s = __fadd_rn(s, __fmul_rn(zr[i], zr[i]));
        s_zsq[tid] = s;
    }
    __syncthreads();

    float zsqr[8];
#pragma unroll
    for (int p = 0; p < 8; p++) zsqr[p] = s_zsq[tx + p * 16];

    float best[8];
    int   bidx[8];
#pragma unroll
    for (int p = 0; p < 8; p++) { best[p] = 3.4e38f; bidx[p] = 0; }

    const float* zbase = s_z + tx * ROWF;
    const int xsw = ty & 7;   // swizzle xor, warp-uniform per ty

    for (int t = 0; t < NTILES; ++t) {
        cp_wait0();
        __syncthreads();   // tile t resident; prior buffer reads all done

        // prefetch tile t+1 into the other buffer (overlaps compute below)
        if (t + 1 < NTILES) {
            u32 bufo = (u32)(((t + 1) & 1) * (TILE_C * DIMS * 4));
            const float* g = cb + (size_t)(t + 1) * TILE_C * DIMS;
#pragma unroll
            for (int i = 0; i < 8; i++) {
                int kc = kc_pf + i * 16;
                u32 dst = s_cb_u + bufo + (u32)(kc * 256 + ((q_pf ^ (kc & 7)) << 4));
                cp_async16(dst, g + (size_t)kc * DIMS + q_pf * 4);
            }
            cp_commit();
        }

        const float* cbuf = s_cb + (t & 1) * (TILE_C * DIMS) + ty * DIMS;

        u64 acc[8][8];
#pragma unroll
        for (int p = 0; p < 8; p++)
#pragma unroll
            for (int c = 0; c < 8; c++) acc[p][c] = 0ull;

#pragma unroll 4
        for (int dpc = 0; dpc < 16; ++dpc) {     // 16B chunk = dims 4dpc..4dpc+3
            u64 zv0[8], zv1[8];
#pragma unroll
            for (int p = 0; p < 8; p++) {
                const float* zp = zbase + p * (16 * ROWF) + dpc * 4;
                zv0[p] = *(const u64*)(zp);
                zv1[p] = *(const u64*)(zp + 2);
            }
            ulonglong2 cv[8];
            const int sq = (dpc ^ xsw) << 2;     // float offset in 64-float row
#pragma unroll
            for (int c = 0; c < 8; c++)
                cv[c] = *(const ulonglong2*)(cbuf + c * (16 * DIMS) + sq);
#pragma unroll
            for (int p = 0; p < 8; p++)
#pragma unroll
                for (int c = 0; c < 8; c++) {
                    acc[p][c] = fma2(zv0[p], cv[c].x, acc[p][c]);
                    acc[p][c] = fma2(zv1[p], cv[c].y, acc[p][c]);
                }
        }

        // epilogue: 64 dists, exact reference rounding
#pragma unroll
        for (int c = 0; c < 8; c++) {
            const int code = t * TILE_C + c * 16 + ty;
            const float csq = s_csq[code];
#pragma unroll
            for (int p = 0; p < 8; p++) {
                float lo, hi;
                unpack2(acc[p][c], lo, hi);
                float dot = __fadd_rn(lo, hi);
                float d = __fadd_rn(__fmaf_rn(-2.f, dot, zsqr[p]), csq);
                if (d < best[p]) { best[p] = d; bidx[p] = code; }
            }
        }
    }

    // --- cross-ty argmin: packed (dist_bits<<32)|idx u64 min (dist2 > 0) ---
    __syncthreads();
    u64* s_red = (u64*)s_cb;   // reuse cb buffers (needs 128*17*8 = 17408 B)
#pragma unroll
    for (int p = 0; p < 8; p++)
        s_red[(tx + p * 16) * 17 + ty] =
            (((u64)__float_as_uint(best[p])) << 32) | (u32)bidx[p];
    __syncthreads();

    int* s_idx = (int*)s_zsq;  // reuse zsq region (128 ints)
    if (tid < PTB) {
        u64 m = s_red[tid * 17];
#pragma unroll
        for (int j = 1; j < 16; j++) {
            u64 v = s_red[tid * 17 + j];
            if (v < m) m = v;
        }
        int idx = (int)(m & 0xffffffffu);
        s_idx[tid] = idx;
        if (base + tid < N)
            out[(size_t)N * DIMS + base + tid] = (float)idx;
    }
    __syncthreads();

    // --- gather z_q = codebook[idx] (bitwise exact) ---
    {
        const float4* cb4 = (const float4*)cb;
        float4* o4 = (float4*)out;
#pragma unroll
        for (int i = 0; i < 8; i++) {
            int e  = tid + i * TPB;
            int pt = e >> 4;
            int q  = e & 15;
            if (base + pt < N)
                o4[(size_t)(base + pt) * 16 + q] = cb4[(size_t)s_idx[pt] * 16 + q];
        }
    }
}

// ---------------------------------------------------------------------------
extern "C" void kernel_launch(void* const* d_in, const int* in_sizes, int n_in,
                              void* d_out, int out_size) {
    const float* z_e = (const float*)d_in[0];
    const float* cb  = (const float*)d_in[1];
    float* out = (float*)d_out;
    const int N = in_sizes[0] / DIMS;

    cbsq_kernel<<<(KCODES + 255) / 256, 256>>>(cb);

    cudaFuncSetAttribute(vq_kernel, cudaFuncAttributeMaxDynamicSharedMemorySize,
                         SMEM_BYTES);
    const int grid = (N + PTB - 1) / PTB;
    vq_kernel<<<grid, TPB, SMEM_BYTES>>>(z_e, cb, out, N);
}

// round 10
// speedup vs baseline: 1.0558x; 1.0001x over previous
#include <cuda_runtime.h>

// VectorQuantizer: N=262144 points (D=64), K=1024 codes.
// out = [ z_q (N*64 floats) | encoding_inds as float (N) ]
//
// Round 7: R4's 8x8 fma2 register tile + conflict-free z (ROWF=66), plus:
//  - codebook tiles double-buffered via cp.async (16B, XOR-swizzled chunks:
//    phys q^(kc&7) on natural 256B rows -> aligned stores AND conflict-free
//    broadcast LDS.128 reads), staging overlapped with compute
//  - one __syncthreads per tile
//  - inner loop per 16B chunk (2 dim-pairs): 16 LDS.64 (z) + 8 LDS.128 (cb)
//    -> 128 fma2
// Score keeps reference rounding exactly:
//   dist2 = fl( fl(zsq - 2*dot) + cb_sq ), argmin first-index tie-break.

#define DIMS    64
#define KCODES  1024
#define TPB     256
#define PTB     128               // points per block
#define TILE_C  128               // codes per smem tile
#define NTILES  (KCODES / TILE_C) // 8
#define ROWF    66                // z row stride (floats), 66%32=2

// SMEM float offsets
#define OFF_Z    0                          // PTB*ROWF = 8448
#define OFF_CSQ  (PTB * ROWF)               // 1024
#define OFF_ZSQ  (OFF_CSQ + KCODES)         // 128
#define OFF_CB   ((OFF_ZSQ + PTB + 3) & ~3) // 2 * TILE_C*DIMS = 16384 (16B aligned)
#define SMEM_FLOATS (OFF_CB + 2 * TILE_C * DIMS)
#define SMEM_BYTES  (SMEM_FLOATS * 4)       // ~104 KB

typedef unsigned long long u64;
typedef unsigned int u32;

__device__ float g_cbsq[KCODES];

static __device__ __forceinline__ void unpack2(u64 v, float& lo, float& hi) {
    u32 a, b;
    asm("mov.b64 {%0, %1}, %2;" : "=r"(a), "=r"(b) : "l"(v));
    lo = __uint_as_float(a);
    hi = __uint_as_float(b);
}
static __device__ __forceinline__ u64 fma2(u64 a, u64 b, u64 c) {
    u64 d;
    asm("fma.rn.f32x2 %0, %1, %2, %3;" : "=l"(d) : "l"(a), "l"(b), "l"(c));
    return d;
}
static __device__ __forceinline__ void cp_async16(u32 saddr, const void* gaddr) {
    asm volatile("cp.async.cg.shared.global [%0], [%1], 16;"
                 :: "r"(saddr), "l"(gaddr));
}
static __device__ __forceinline__ void cp_commit() {
    asm volatile("cp.async.commit_group;");
}
static __device__ __forceinline__ void cp_wait0() {
    asm volatile("cp.async.wait_group 0;" ::: "memory");
}

// ---------------------------------------------------------------------------
// cb_sq[k] = sequential fp32 sum of squares of codebook row k (matches ref).
__global__ void cbsq_kernel(const float* __restrict__ cb) {
    int k = blockIdx.x * blockDim.x + threadIdx.x;
    if (k < KCODES) {
        const float* r = cb + (size_t)k * DIMS;
        float s = 0.f;
#pragma unroll
        for (int i = 0; i < DIMS; i++)
            s = __fadd_rn(s, __fmul_rn(r[i], r[i]));
        g_cbsq[k] = s;
    }
}

// ---------------------------------------------------------------------------
__global__ __launch_bounds__(TPB, 1)
void vq_kernel(const float* __restrict__ z_e,
               const float* __restrict__ cb,
               float* __restrict__ out,
               int N) {
    extern __shared__ float smem[];
    float* s_z   = smem + OFF_Z;    // [PTB][ROWF]
    float* s_csq = smem + OFF_CSQ;  // [KCODES]
    float* s_zsq = smem + OFF_ZSQ;  // [PTB]
    float* s_cb  = smem + OFF_CB;   // 2 x [TILE_C][64], 16B-chunk swizzled

    const int tid = threadIdx.x;
    const int tx  = tid & 15;   // point lane: pts tx + p*16
    const int ty  = tid >> 4;   // code lane:  codes ty + c*16 (per tile)
    const int base = blockIdx.x * PTB;

    const u32 s_cb_u = (u32)__cvta_generic_to_shared(s_cb);
    const int kc_pf = tid >> 4;        // code row this thread prefetches
    const int q_pf  = tid & 15;        // 16B chunk index
    const u32 pf_dst_off = (u32)(kc_pf * 256 + ((q_pf ^ (kc_pf & 7)) << 4));
    const size_t pf_src_off = (size_t)kc_pf * DIMS + q_pf * 4;

    // --- prefetch codebook tile 0 into buffer 0 ---
#pragma unroll
    for (int i = 0; i < 8; i++) {
        // e = tid + i*256 -> kc = kc_pf + i*16, q = q_pf
        int kc = kc_pf + i * 16;
        u32 dst = s_cb_u + (u32)(kc * 256 + ((q_pf ^ (kc & 7)) << 4));
        cp_async16(dst, cb + (size_t)kc * DIMS + q_pf * 4);
    }
    cp_commit();

    // --- stage z tile [PTB x DIMS] into padded rows; also csq ---
    {
        const float4* z4 = (const float4*)z_e;
        const int lim4 = (N * DIMS) / 4;
#pragma unroll
        for (int i = 0; i < 8; i++) {
            int e  = tid + i * TPB;      // 0..2047
            int pt = e >> 4;
            int q  = e & 15;
            float4 v;
            int g = (base + pt) * 16 + q;
            if (g < lim4) v = z4[g];
            else { v.x = v.y = v.z = v.w = 0.f; }
            float* dst = s_z + pt * ROWF + q * 4;
            *(float2*)(dst)     = make_float2(v.x, v.y);
            *(float2*)(dst + 2) = make_float2(v.z, v.w);
        }
#pragma unroll
        for (int i = 0; i < 4; i++)
            s_csq[tid + i * TPB] = g_cbsq[tid + i * TPB];
    }
    __syncthreads();

    // zsq per point (sequential fp32, matches reference path)
    if (tid < PTB) {
        const float* zr = s_z + tid * ROWF;
        float s = 0.f;
#pragma unroll
        for (int i = 0; i < DIMS; i++)
            s = __fadd_rn(s, __fmul_rn(zr[i], zr[i]));
        s_zsq[tid] = s;
    }
    __syncthreads();

    float zsqr[8];
#pragma unroll
    for (int p = 0; p < 8; p++) zsqr[p] = s_zsq[tx + p * 16];

    float best[8];
    int   bidx[8];
#pragma unroll
    for (int p = 0; p < 8; p++) { best[p] = 3.4e38f; bidx[p] = 0; }

    const float* zbase = s_z + tx * ROWF;
    const int xsw = ty & 7;   // swizzle xor, warp-uniform per ty

    for (int t = 0; t < NTILES; ++t) {
        cp_wait0();
        __syncthreads();   // tile t resident; prior buffer reads all done

        // prefetch tile t+1 into the other buffer (overlaps compute below)
        if (t + 1 < NTILES) {
            u32 bufo = (u32)(((t + 1) & 1) * (TILE_C * DIMS * 4));
            const float* g = cb + (size_t)(t + 1) * TILE_C * DIMS;
#pragma unroll
            for (int i = 0; i < 8; i++) {
                int kc = kc_pf + i * 16;
                u32 dst = s_cb_u + bufo + (u32)(kc * 256 + ((q_pf ^ (kc & 7)) << 4));
                cp_async16(dst, g + (size_t)kc * DIMS + q_pf * 4);
            }
            cp_commit();
        }

        const float* cbuf = s_cb + (t & 1) * (TILE_C * DIMS) + ty * DIMS;

        u64 acc[8][8];
#pragma unroll
        for (int p = 0; p < 8; p++)
#pragma unroll
            for (int c = 0; c < 8; c++) acc[p][c] = 0ull;

#pragma unroll 4
        for (int dpc = 0; dpc < 16; ++dpc) {     // 16B chunk = dims 4dpc..4dpc+3
            u64 zv0[8], zv1[8];
#pragma unroll
            for (int p = 0; p < 8; p++) {
                const float* zp = zbase + p * (16 * ROWF) + dpc * 4;
                zv0[p] = *(const u64*)(zp);
                zv1[p] = *(const u64*)(zp + 2);
            }
            ulonglong2 cv[8];
            const int sq = (dpc ^ xsw) << 2;     // float offset in 64-float row
#pragma unroll
            for (int c = 0; c < 8; c++)
                cv[c] = *(const ulonglong2*)(cbuf + c * (16 * DIMS) + sq);
#pragma unroll
            for (int p = 0; p < 8; p++)
#pragma unroll
                for (int c = 0; c < 8; c++) {
                    acc[p][c] = fma2(zv0[p], cv[c].x, acc[p][c]);
                    acc[p][c] = fma2(zv1[p], cv[c].y, acc[p][c]);
                }
        }

        // epilogue: 64 dists, exact reference rounding
#pragma unroll
        for (int c = 0; c < 8; c++) {
            const int code = t * TILE_C + c * 16 + ty;
            const float csq = s_csq[code];
#pragma unroll
            for (int p = 0; p < 8; p++) {
                float lo, hi;
                unpack2(acc[p][c], lo, hi);
                float dot = __fadd_rn(lo, hi);
                float d = __fadd_rn(__fmaf_rn(-2.f, dot, zsqr[p]), csq);
                if (d < best[p]) { best[p] = d; bidx[p] = code; }
            }
        }
    }

    // --- cross-ty argmin: packed (dist_bits<<32)|idx u64 min (dist2 > 0) ---
    __syncthreads();
    u64* s_red = (u64*)s_cb;   // reuse cb buffers (needs 128*17*8 = 17408 B)
#pragma unroll
    for (int p = 0; p < 8; p++)
        s_red[(tx + p * 16) * 17 + ty] =
            (((u64)__float_as_uint(best[p])) << 32) | (u32)bidx[p];
    __syncthreads();

    int* s_idx = (int*)s_zsq;  // reuse zsq region (128 ints)
    if (tid < PTB) {
        u64 m = s_red[tid * 17];
#pragma unroll
        for (int j = 1; j < 16; j++) {
            u64 v = s_red[tid * 17 + j];
            if (v < m) m = v;
        }
        int idx = (int)(m & 0xffffffffu);
        s_idx[tid] = idx;
        if (base + tid < N)
            out[(size_t)N * DIMS + base + tid] = (float)idx;
    }
    __syncthreads();

    // --- gather z_q = codebook[idx] (bitwise exact) ---
    {
        const float4* cb4 = (const float4*)cb;
        float4* o4 = (float4*)out;
#pragma unroll
        for (int i = 0; i < 8; i++) {
            int e  = tid + i * TPB;
            int pt = e >> 4;
            int q  = e & 15;
            if (base + pt < N)
                o4[(size_t)(base + pt) * 16 + q] = cb4[(size_t)s_idx[pt] * 16 + q];
        }
    }
}

// ---------------------------------------------------------------------------
extern "C" void kernel_launch(void* const* d_in, const int* in_sizes, int n_in,
                              void* d_out, int out_size) {
    const float* z_e = (const float*)d_in[0];
    const float* cb  = (const float*)d_in[1];
    float* out = (float*)d_out;
    const int N = in_sizes[0] / DIMS;

    cbsq_kernel<<<(KCODES + 255) / 256, 256>>>(cb);

    cudaFuncSetAttribute(vq_kernel, cudaFuncAttributeMaxDynamicSharedMemorySize,
                         SMEM_BYTES);
    const int grid = (N + PTB - 1) / PTB;
    vq_kernel<<<grid, TPB, SMEM_BYTES>>>(z_e, cb, out, N);
}